// round 8
// baseline (speedup 1.0000x reference)
#include <cuda_runtime.h>

#define NE 8
#define DIM 1024
#define NT 256              // 8 warps per CTA, one row per warp
#define VF4 (DIM / 4)       // 256 float4 per vector
#define NCH 8               // chunks per row (32 float4 per chunk per vector)
#define NG 36               // lower triangle of 8x8

__device__ __forceinline__ constexpr int tri(int i, int j) { return i * (i + 1) / 2 + j; }

__global__ __launch_bounds__(NT, 2) void warp_gs_kernel(
    const float* __restrict__ x, float* __restrict__ out, int batch) {
    const int lane = threadIdx.x & 31;
    const int warp = threadIdx.x >> 5;
    const int row = blockIdx.x * (NT / 32) + warp;
    if (row >= batch) return;

    const float4* __restrict__ xin =
        reinterpret_cast<const float4*>(x + (size_t)row * NE * DIM);
    float4* __restrict__ xout =
        reinterpret_cast<float4*>(out + (size_t)row * NE * DIM);

    // ================= Pass A: Gram accumulation, double-buffered =================
    float g[NG];
#pragma unroll
    for (int k = 0; k < NG; k++) g[k] = 0.0f;

    float4 buf[2][NE];
#pragma unroll
    for (int i = 0; i < NE; i++) buf[0][i] = __ldcg(&xin[i * VF4 + lane]);

#pragma unroll
    for (int c = 0; c < NCH; c++) {
        const int cur = c & 1;
        if (c < NCH - 1) {
#pragma unroll
            for (int i = 0; i < NE; i++)
                buf[cur ^ 1][i] = __ldcg(&xin[i * VF4 + (c + 1) * 32 + lane]);
        }
#pragma unroll
        for (int i = 0; i < NE; i++) {
#pragma unroll
            for (int j = 0; j <= i; j++) {
                g[tri(i, j)] += buf[cur][i].x * buf[cur][j].x +
                                buf[cur][i].y * buf[cur][j].y +
                                buf[cur][i].z * buf[cur][j].z +
                                buf[cur][i].w * buf[cur][j].w;
            }
        }
    }

    // ============ Butterfly reduce: every lane gets the full Gram matrix ==========
#pragma unroll
    for (int k = 0; k < NG; k++) {
#pragma unroll
        for (int o = 16; o > 0; o >>= 1)
            g[k] += __shfl_xor_sync(0xffffffffu, g[k], o);
    }

    // ========= Per-lane coefficient-space Gram-Schmidt: W lower-triangular ========
    float W[NG];
    W[0] = rsqrtf(g[0]);
#pragma unroll
    for (int i = 1; i < NE; i++) {
        float c[NE - 1];
#pragma unroll
        for (int k = 0; k < NE - 1; k++) {
            if (k < i) {
                float s = 0.f;
#pragma unroll
                for (int j = 0; j < NE - 1; j++)
                    if (j <= k) s += W[tri(k, j)] * g[tri(i, j)];
                c[k] = s;
            }
        }
        float n2 = g[tri(i, i)];
#pragma unroll
        for (int k = 0; k < NE - 1; k++)
            if (k < i) n2 -= c[k] * c[k];
        const float inv = rsqrtf(n2);
#pragma unroll
        for (int j = 0; j < NE - 1; j++) {
            if (j < i) {
                float s = 0.f;
#pragma unroll
                for (int k = 0; k < NE - 1; k++)
                    if (k >= j && k < i) s += c[k] * W[tri(k, j)];
                W[tri(i, j)] = -inv * s;
            }
        }
        W[tri(i, i)] = inv;
    }

    // ============ Pass B: re-read (L2 hits), combine, store; double-buffered ======
#pragma unroll
    for (int i = 0; i < NE; i++) buf[0][i] = __ldcg(&xin[i * VF4 + lane]);

#pragma unroll
    for (int c = 0; c < NCH; c++) {
        const int cur = c & 1;
        if (c < NCH - 1) {
#pragma unroll
            for (int i = 0; i < NE; i++)
                buf[cur ^ 1][i] = __ldcg(&xin[i * VF4 + (c + 1) * 32 + lane]);
        }
#pragma unroll
        for (int i = 0; i < NE; i++) {
            float4 o = make_float4(0.f, 0.f, 0.f, 0.f);
#pragma unroll
            for (int j = 0; j < NE; j++) {
                if (j <= i) {
                    const float wj = W[tri(i, j)];
                    o.x += wj * buf[cur][j].x;
                    o.y += wj * buf[cur][j].y;
                    o.z += wj * buf[cur][j].z;
                    o.w += wj * buf[cur][j].w;
                }
            }
            __stcs(&xout[i * VF4 + c * 32 + lane], o);
        }
    }
}

extern "C" void kernel_launch(void* const* d_in, const int* in_sizes, int n_in,
                              void* d_out, int out_size) {
    const float* x = (const float*)d_in[0];
    float* out = (float*)d_out;
    const int batch = in_sizes[0] / (NE * DIM);  // 8192
    const int rows_per_cta = NT / 32;            // 8
    const int grid = (batch + rows_per_cta - 1) / rows_per_cta;
    warp_gs_kernel<<<grid, NT>>>(x, out, batch);
}

// round 9
// speedup vs baseline: 1.3843x; 1.3843x over previous
#include <cuda_runtime.h>

#define NE 8
#define DIM 1024
#define NT 256
#define F4 (DIM / 4)
#define NG 36     // lower triangle of 8x8 Gram
#define RW 132    // 128 partials + 4 pad -> 16B-aligned rows, conflict-free float4

__device__ __forceinline__ constexpr int tri(int i, int j) { return i * (i + 1) / 2 + j; }

__global__ __launch_bounds__(NT, 3) void gram_gs_kernel(
    const float* __restrict__ x, float* __restrict__ out) {
    const int t = threadIdx.x;
    const int warp = t >> 5;
    const int lane = t & 31;

    __shared__ float red[NG][RW];  // 18.6 KB
    __shared__ float gf_s[NG];

    const float4* __restrict__ xin =
        reinterpret_cast<const float4*>(x + (size_t)blockIdx.x * NE * DIM);
    float4* __restrict__ xout =
        reinterpret_cast<float4*>(out + (size_t)blockIdx.x * NE * DIM);

    // ---- Load all 8 expert slices (coalesced LDG.128, front-batched) ----
    float4 v[NE];
#pragma unroll
    for (int i = 0; i < NE; i++) v[i] = xin[i * F4 + t];

    // ---- Gram partials: 1-level shuffle, lanes 0-15 publish 128 partials/value ----
#pragma unroll
    for (int i = 0; i < NE; i++) {
#pragma unroll
        for (int j = 0; j <= i; j++) {
            float s = v[i].x * v[j].x + v[i].y * v[j].y +
                      v[i].z * v[j].z + v[i].w * v[j].w;
            s += __shfl_xor_sync(0xffffffffu, s, 16);
            if (lane < 16) red[tri(i, j)][warp * 16 + lane] = s;
        }
    }
    __syncthreads();

    // ---- Warp-parallel tail: warp w reduces values k = w, w+8, ..., via LDS.128 ----
#pragma unroll
    for (int q = 0; q < 5; q++) {
        const int k = warp + 8 * q;
        if (k < NG) {
            const float4 r = *reinterpret_cast<const float4*>(&red[k][lane * 4]);
            float s = (r.x + r.y) + (r.z + r.w);
#pragma unroll
            for (int o = 16; o > 0; o >>= 1)
                s += __shfl_xor_sync(0xffffffffu, s, o);
            if (lane == 0) gf_s[k] = s;
        }
    }
    __syncthreads();

    // ---- Gram-Schmidt in coefficient space; W in regs, g read from smem (broadcast) ----
    float W[NG];
    {
        float inv = rsqrtf(gf_s[0]);
        W[0] = inv;
        float4 o;
        o.x = inv * v[0].x; o.y = inv * v[0].y;
        o.z = inv * v[0].z; o.w = inv * v[0].w;
        xout[t] = o;
    }

#pragma unroll
    for (int i = 1; i < NE; i++) {
        float gi[NE];
#pragma unroll
        for (int j = 0; j < NE; j++)
            if (j <= i) gi[j] = gf_s[tri(i, j)];

        float c[NE - 1];
#pragma unroll
        for (int k = 0; k < NE - 1; k++) {
            if (k < i) {
                float s = 0.f;
#pragma unroll
                for (int j = 0; j < NE - 1; j++)
                    if (j <= k) s += W[tri(k, j)] * gi[j];
                c[k] = s;
            }
        }
        float n2 = gi[i];
#pragma unroll
        for (int k = 0; k < NE - 1; k++)
            if (k < i) n2 -= c[k] * c[k];
        const float inv = rsqrtf(n2);
#pragma unroll
        for (int j = 0; j < NE - 1; j++) {
            if (j < i) {
                float s = 0.f;
#pragma unroll
                for (int k = 0; k < NE - 1; k++)
                    if (k >= j && k < i) s += c[k] * W[tri(k, j)];
                W[tri(i, j)] = -inv * s;
            }
        }
        W[tri(i, i)] = inv;

        // Fused output row i = sum_{j<=i} W[i][j] * v_j
        float4 o = make_float4(0.f, 0.f, 0.f, 0.f);
#pragma unroll
        for (int j = 0; j < NE; j++) {
            if (j <= i) {
                const float wj = W[tri(i, j)];
                o.x += wj * v[j].x;
                o.y += wj * v[j].y;
                o.z += wj * v[j].z;
                o.w += wj * v[j].w;
            }
        }
        xout[i * F4 + t] = o;
    }
}

extern "C" void kernel_launch(void* const* d_in, const int* in_sizes, int n_in,
                              void* d_out, int out_size) {
    const float* x = (const float*)d_in[0];
    float* out = (float*)d_out;
    const int batch = in_sizes[0] / (NE * DIM);  // 8192
    gram_gs_kernel<<<batch, NT>>>(x, out);
}